// round 16
// baseline (speedup 1.0000x reference)
#include <cuda_runtime.h>

#define DIM 2048
#define SEQ 8192
#define NH 16
#define HD 128
#define PD 512
#define LNEPS 1e-5f
#define RSQRT_D 0.08838834764831845f  /* 1/sqrt(128) */

#define LKS 8     /* logits k-split */
#define LKC 256   /* k per chunk */
#define LKT 16    /* k per smem tile */
#define LM  256   /* rows per logits CTA */

#define CS   64   /* ctx: seq rows per chunk */
#define NCH  128  /* ctx chunks */

// ---------------- static scratch ----------------
__device__ __align__(16) float g_qW[NH * DIM];
__device__ __align__(16) float g_logP[LKS][NH * SEQ];     // 4 MB
__device__ __align__(16) float g_attn[NH * SEQ];
__device__ __align__(16) float g_partial[NCH * NH * DIM]; // 16 MB
__device__ __align__(16) float g_ctx8[8][NH * DIM];       // 1 MB (ctxred stage A)
__device__ __align__(16) float g_ctx[NH * DIM];
__device__ __align__(16) float g_x1[DIM];
__device__ __align__(16) float g_h1[PD];
__device__ __align__(16) float g_h1n[PD];
__device__ __align__(16) float g_y[DIM];
__device__ int g_barcnt;
__device__ int g_ack;

// ---- K0: qW[h][j] = sum_d q[h*128+d] * W_kv[h*128+d][j] ----
__global__ void __launch_bounds__(256) k_qw(const float* __restrict__ q,
                                            const float* __restrict__ Wkv) {
    int tid = blockIdx.x * 256 + threadIdx.x;   // 0..32767
    int h = tid >> 11;
    int j = tid & (DIM - 1);
    const float* qh = q + h * HD;
    const float* wcol = Wkv + (size_t)(h * HD) * DIM + j;
    float acc = 0.f;
#pragma unroll 16
    for (int d = 0; d < HD; d++)
        acc += qh[d] * wcol[(size_t)d * DIM];
    g_qW[tid] = acc;
}

// ---- K1: logits partials, double-buffered smem pipeline ----
// grid (32, 8), 256 thr. Tile M=256 x N=16, Kchunk=256, 16-k tiles.
__global__ void __launch_bounds__(256) k_logits(const float* __restrict__ x) {
    __shared__ float xs[2][LKT][LM + 4];   // 2 x [k][r]
    __shared__ float qs[LKC][20];          // [k][h]
    int t = threadIdx.x;
    int s0 = blockIdx.x * LM;
    int k0 = blockIdx.y * LKC;
    int rr = t >> 2;   // 0..63
    int kq = t & 3;    // 0..3
#pragma unroll
    for (int i = 0; i < 16; i++) {
        int idx = t + i * 256;           // 0..4095
        int k = idx & 255, h = idx >> 8;
        qs[k][h] = g_qW[h * DIM + k0 + k];
    }
    float acc[4][4];
#pragma unroll
    for (int i = 0; i < 4; i++)
#pragma unroll
        for (int j = 0; j < 4; j++) acc[i][j] = 0.f;

    const float* xb = x + (size_t)s0 * DIM + k0 + kq * 4;

    // prime tile 0
    float4 v[4];
#pragma unroll
    for (int m = 0; m < 4; m++)
        v[m] = *reinterpret_cast<const float4*>(xb + (size_t)(rr + 64 * m) * DIM);
#pragma unroll
    for (int m = 0; m < 4; m++) {
        int r = rr + 64 * m;
        xs[0][kq * 4 + 0][r] = v[m].x;
        xs[0][kq * 4 + 1][r] = v[m].y;
        xs[0][kq * 4 + 2][r] = v[m].z;
        xs[0][kq * 4 + 3][r] = v[m].w;
    }
    __syncthreads();

    for (int it = 0; it < LKC / LKT; it++) {     // 16 tiles
        int buf = it & 1;
        if (it < LKC / LKT - 1) {
#pragma unroll
            for (int m = 0; m < 4; m++)
                v[m] = *reinterpret_cast<const float4*>(
                    xb + (it + 1) * LKT + (size_t)(rr + 64 * m) * DIM);
        }
#pragma unroll
        for (int k = 0; k < LKT; k++) {
            float4 xv = *reinterpret_cast<const float4*>(&xs[buf][k][rr * 4]);
            float4 qv = *reinterpret_cast<const float4*>(&qs[it * LKT + k][kq * 4]);
            float ax[4] = {xv.x, xv.y, xv.z, xv.w};
            float aq[4] = {qv.x, qv.y, qv.z, qv.w};
#pragma unroll
            for (int i = 0; i < 4; i++)
#pragma unroll
                for (int j = 0; j < 4; j++) acc[i][j] += ax[i] * aq[j];
        }
        if (it < LKC / LKT - 1) {
#pragma unroll
            for (int m = 0; m < 4; m++) {
                int r = rr + 64 * m;
                xs[buf ^ 1][kq * 4 + 0][r] = v[m].x;
                xs[buf ^ 1][kq * 4 + 1][r] = v[m].y;
                xs[buf ^ 1][kq * 4 + 2][r] = v[m].z;
                xs[buf ^ 1][kq * 4 + 3][r] = v[m].w;
            }
        }
        __syncthreads();
    }
#pragma unroll
    for (int j = 0; j < 4; j++) {
        float4 o = make_float4(acc[0][j], acc[1][j], acc[2][j], acc[3][j]);
        *reinterpret_cast<float4*>(
            &g_logP[blockIdx.y][(kq * 4 + j) * SEQ + s0 + rr * 4]) = o;
    }
}

// ---- K2: softmax per head (sums k-split partials, applies 1/sqrt(d)) ----
__global__ void __launch_bounds__(1024) k_softmax() {
    __shared__ float red[32];
    int h = blockIdx.x, t = threadIdx.x;
    float vals[8];
    float m = -1e30f;
#pragma unroll
    for (int i = 0; i < 8; i++) {
        int idx = t + i * 1024;
        float v = 0.f;
#pragma unroll
        for (int ks = 0; ks < LKS; ks++) v += g_logP[ks][h * SEQ + idx];
        v *= RSQRT_D;
        vals[i] = v;
        m = fmaxf(m, v);
    }
#pragma unroll
    for (int o = 16; o; o >>= 1) m = fmaxf(m, __shfl_xor_sync(0xffffffffu, m, o));
    if ((t & 31) == 0) red[t >> 5] = m;
    __syncthreads();
    m = red[0];
#pragma unroll
    for (int i = 1; i < 32; i++) m = fmaxf(m, red[i]);

    float sum = 0.f;
#pragma unroll
    for (int i = 0; i < 8; i++) { vals[i] = __expf(vals[i] - m); sum += vals[i]; }
#pragma unroll
    for (int o = 16; o; o >>= 1) sum += __shfl_xor_sync(0xffffffffu, sum, o);
    __syncthreads();
    if ((t & 31) == 0) red[t >> 5] = sum;
    __syncthreads();
    float tot = 0.f;
#pragma unroll
    for (int i = 0; i < 32; i++) tot += red[i];
    float rinv = 1.0f / tot;
#pragma unroll
    for (int i = 0; i < 8; i++) g_attn[h * SEQ + t + i * 1024] = vals[i] * rinv;
}

// ---- K3: ctx partials = attn @ x, all 16 heads, single x pass ----
// grid (128, 2): s-chunk (64 rows) x j-half (1024 cols). 256 thr, 2 CTAs/SM.
__global__ void __launch_bounds__(256, 2) k_ctx(const float* __restrict__ x) {
    __shared__ float as[NH][CS];
    int t = threadIdx.x;
    int s0 = blockIdx.x * CS;
    int j = blockIdx.y * 1024 + t * 4;

#pragma unroll
    for (int i = 0; i < 4; i++) {
        int idx = t + i * 256;            // 0..1023
        int h = idx >> 6, s = idx & 63;
        as[h][s] = g_attn[h * SEQ + s0 + s];
    }
    __syncthreads();

    float4 acc[NH];
#pragma unroll
    for (int h = 0; h < NH; h++) acc[h] = make_float4(0.f, 0.f, 0.f, 0.f);

    const float* xb = x + (size_t)s0 * DIM + j;

    float4 xc[4];
#pragma unroll
    for (int r = 0; r < 4; r++)
        xc[r] = *reinterpret_cast<const float4*>(xb + (size_t)r * DIM);

    for (int sb = 0; sb < CS; sb += 4) {
        int nsb = (sb + 4 < CS) ? (sb + 4) : sb;
        float4 xn[4];
#pragma unroll
        for (int r = 0; r < 4; r++)
            xn[r] = *reinterpret_cast<const float4*>(xb + (size_t)(nsb + r) * DIM);

#pragma unroll
        for (int hq = 0; hq < 4; hq++) {
            float4 a4[4];
#pragma unroll
            for (int hh = 0; hh < 4; hh++)
                a4[hh] = *reinterpret_cast<const float4*>(&as[hq * 4 + hh][sb]);
#pragma unroll
            for (int ss = 0; ss < 4; ss++) {
                float4 xv = xc[ss];
#pragma unroll
                for (int hh = 0; hh < 4; hh++) {
                    float a = (ss == 0) ? a4[hh].x : (ss == 1) ? a4[hh].y
                            : (ss == 2) ? a4[hh].z : a4[hh].w;
                    acc[hq * 4 + hh].x += a * xv.x;
                    acc[hq * 4 + hh].y += a * xv.y;
                    acc[hq * 4 + hh].z += a * xv.z;
                    acc[hq * 4 + hh].w += a * xv.w;
                }
            }
        }
#pragma unroll
        for (int r = 0; r < 4; r++) xc[r] = xn[r];
    }

    float* P = g_partial + (size_t)blockIdx.x * NH * DIM;
#pragma unroll
    for (int h = 0; h < NH; h++)
        *reinterpret_cast<float4*>(&P[h * DIM + j]) = acc[h];
}

// ---- K4: fused tail: ctxred + vproj + proj1 + ln + proj2 ----
// grid 256 x 256 thr, all CTAs co-resident; device spin barriers between phases.
__device__ __forceinline__ void gbar(int target) {
    __syncthreads();
    if (threadIdx.x == 0) {
        __threadfence();
        atomicAdd(&g_barcnt, 1);
        while (atomicAdd(&g_barcnt, 0) < target) {}
        __threadfence();
    }
    __syncthreads();
}

__global__ void __launch_bounds__(256) k_tail(const float* __restrict__ Wkv,
                                              const float* __restrict__ bkv,
                                              const float* __restrict__ Wp1,
                                              const float* __restrict__ bp1,
                                              const float* __restrict__ lnw,
                                              const float* __restrict__ lnb,
                                              const float* __restrict__ Wp2,
                                              const float* __restrict__ bp2) {
    int t = threadIdx.x;
    int g = blockIdx.x * 256 + t;      // 0..65535
    int w = g >> 5;                    // warp id 0..2047
    int l = t & 31;

    // P0a: partial chunk reduction: 8 parts x 8192 float4 outputs
    {
        int part = g >> 13;            // 0..7
        int idx = g & 8191;            // float4 index
        float4 a = make_float4(0.f, 0.f, 0.f, 0.f);
#pragma unroll
        for (int c = 0; c < 16; c++) {
            float4 p = *reinterpret_cast<const float4*>(
                &g_partial[(size_t)(part * 16 + c) * NH * DIM + idx * 4]);
            a.x += p.x; a.y += p.y; a.z += p.z; a.w += p.w;
        }
        *reinterpret_cast<float4*>(&g_ctx8[part][idx * 4]) = a;
    }
    gbar(256);

    // P0b: final 8-way reduction -> g_ctx
    if (g < 8192) {
        float4 a = make_float4(0.f, 0.f, 0.f, 0.f);
#pragma unroll
        for (int p = 0; p < 8; p++) {
            float4 v = *reinterpret_cast<const float4*>(&g_ctx8[p][g * 4]);
            a.x += v.x; a.y += v.y; a.z += v.z; a.w += v.w;
        }
        *reinterpret_cast<float4*>(&g_ctx[g * 4]) = a;
    }
    gbar(512);

    // P1: vproj — warp w computes x1[w]
    {
        const float4* w4 = reinterpret_cast<const float4*>(Wkv + (size_t)(DIM + w) * DIM);
        const float4* c4 = reinterpret_cast<const float4*>(g_ctx + (w >> 7) * DIM);
        float a = 0.f;
#pragma unroll
        for (int i = l; i < DIM / 4; i += 32) {
            float4 wv = w4[i], cv = c4[i];
            a += wv.x * cv.x + wv.y * cv.y + wv.z * cv.z + wv.w * cv.w;
        }
#pragma unroll
        for (int o = 16; o; o >>= 1) a += __shfl_xor_sync(0xffffffffu, a, o);
        if (l == 0) g_x1[w] = a + bkv[DIM + w];
    }
    gbar(768);

    // P2: proj1 — warps 0..511
    if (w < PD) {
        const float4* w4 = reinterpret_cast<const float4*>(Wp1 + (size_t)w * DIM);
        const float4* x4 = reinterpret_cast<const float4*>(g_x1);
        float a = 0.f;
#pragma unroll
        for (int i = l; i < DIM / 4; i += 32) {
            float4 wv = w4[i], xv = x4[i];
            a += wv.x * xv.x + wv.y * xv.y + wv.z * xv.z + wv.w * xv.w;
        }
#pragma unroll
        for (int o = 16; o; o >>= 1) a += __shfl_xor_sync(0xffffffffu, a, o);
        if (l == 0) g_h1[w] = a + bp1[w];
    }
    gbar(1024);

    // P3: LayerNorm + ReLU (CTA 0, 2 elems/thread)
    if (blockIdx.x == 0) {
        __shared__ float red[8];
        float v0 = g_h1[t], v1 = g_h1[t + 256];
        float a = v0 + v1;
#pragma unroll
        for (int o = 16; o; o >>= 1) a += __shfl_xor_sync(0xffffffffu, a, o);
        if (l == 0) red[t >> 5] = a;
        __syncthreads();
        float tot = 0.f;
#pragma unroll
        for (int i = 0; i < 8; i++) tot += red[i];
        float mu = tot * (1.0f / (float)PD);
        float d0 = v0 - mu, d1 = v1 - mu;
        float a2 = d0 * d0 + d1 * d1;
#pragma unroll
        for (int o = 16; o; o >>= 1) a2 += __shfl_xor_sync(0xffffffffu, a2, o);
        __syncthreads();
        if (l == 0) red[t >> 5] = a2;
        __syncthreads();
        float tv = 0.f;
#pragma unroll
        for (int i = 0; i < 8; i++) tv += red[i];
        float var = tv * (1.0f / (float)PD);
        float r = rsqrtf(var + LNEPS);
        g_h1n[t] = fmaxf(d0 * r * lnw[t] + lnb[t], 0.0f);
        g_h1n[t + 256] = fmaxf(d1 * r * lnw[t + 256] + lnb[t + 256], 0.0f);
    }
    gbar(1280);

    // P4: proj2 — warp w computes y[w]
    {
        const float4* w4 = reinterpret_cast<const float4*>(Wp2 + (size_t)w * PD);
        const float4* h4 = reinterpret_cast<const float4*>(g_h1n);
        float a = 0.f;
#pragma unroll
        for (int i = l; i < PD / 4; i += 32) {
            float4 wv = w4[i], hv = h4[i];
            a += wv.x * hv.x + wv.y * hv.y + wv.z * hv.z + wv.w * hv.w;
        }
#pragma unroll
        for (int o = 16; o; o >>= 1) a += __shfl_xor_sync(0xffffffffu, a, o);
        if (l == 0) g_y[w] = a + bp2[w];
    }

    // final barrier + counter reset for next graph replay
    __syncthreads();
    if (t == 0) {
        __threadfence();
        atomicAdd(&g_barcnt, 1);
        while (atomicAdd(&g_barcnt, 0) < 1536) {}
        atomicAdd(&g_ack, 1);
        if (blockIdx.x == 0) {
            while (atomicAdd(&g_ack, 0) < 256) {}
            g_barcnt = 0;
            g_ack = 0;
            __threadfence();
        }
    }
}

// ---- K6: out = x + y; streaming stores keep x resident in L2 ----
__global__ void __launch_bounds__(256) k_resid(const float4* __restrict__ x4,
                                               float4* __restrict__ o4) {
    int i = blockIdx.x * 256 + threadIdx.x;
    float4 xv = x4[i];
    float4 yv = *reinterpret_cast<const float4*>(&g_y[(i & 511) * 4]);
    float4 r = make_float4(xv.x + yv.x, xv.y + yv.y, xv.z + yv.z, xv.w + yv.w);
    __stcs(&o4[i], r);
}

// ---------------- launch ----------------
extern "C" void kernel_launch(void* const* d_in, const int* in_sizes, int n_in,
                              void* d_out, int out_size) {
    const float* x   = (const float*)d_in[0];
    const float* q   = (const float*)d_in[1];
    const float* Wkv = (const float*)d_in[2];
    const float* bkv = (const float*)d_in[3];
    const float* Wp1 = (const float*)d_in[4];
    const float* bp1 = (const float*)d_in[5];
    const float* Wp2 = (const float*)d_in[6];
    const float* bp2 = (const float*)d_in[7];
    const float* lnw = (const float*)d_in[8];
    const float* lnb = (const float*)d_in[9];
    float* out = (float*)d_out;

    k_qw<<<(NH * DIM) / 256, 256>>>(q, Wkv);
    k_logits<<<dim3(SEQ / LM, LKS), 256>>>(x);
    k_softmax<<<NH, 1024>>>();
    k_ctx<<<dim3(NCH, 2), 256>>>(x);
    k_tail<<<256, 256>>>(Wkv, bkv, Wp1, bp1, lnw, lnb, Wp2, bp2);
    k_resid<<<(SEQ * DIM / 4) / 256, 256>>>((const float4*)x, (float4*)out);
}